// round 7
// baseline (speedup 1.0000x reference)
#include <cuda_runtime.h>
#include <cuda_bf16.h>
#include <cstdint>

#define TT 512
#define NB 128
#define NSAMP 32768
#define RCTAS 100
#define KC 20
#define KP0 224
#define KP1 416
#define CH 16     // k-chunk per pipeline stage
#define AP2 24    // padded smem stride (bf16 elems) for 16-wide k chunks

// ---------------- static scratch (no allocation) ----------------
__device__ float g_pre_f[(size_t)TT * 800 * NB];   // (t, gate, b)
__device__ float g_pre_b[(size_t)TT * 800 * NB];
__device__ float g_h0[(size_t)TT * 400 * NB];      // layer0 out (t, u, b)
__device__ float g_hbt[(size_t)NB * TT * 400];     // layer1 out (b, t, u)
__device__ float g_hid[(size_t)NSAMP * 200];       // MLP hidden (s, n)
__device__ float g_hbuf0[2 * 200 * NB];            // h ping-pong [dir][u][b]
__device__ float g_hbuf1[2 * 200 * NB];
__device__ unsigned g_barCnt;
__device__ unsigned g_barGen;

// bf16-split operand buffers (hi + lo) for tensor-core GEMMs
__device__ __align__(16) __nv_bfloat16 g_w0h[(size_t)2 * 896 * KP0];  // [dir][m][k]
__device__ __align__(16) __nv_bfloat16 g_w0l[(size_t)2 * 896 * KP0];
__device__ __align__(16) __nv_bfloat16 g_w1h[(size_t)2 * 896 * KP1];
__device__ __align__(16) __nv_bfloat16 g_w1l[(size_t)2 * 896 * KP1];
__device__ __align__(16) __nv_bfloat16 g_xh[(size_t)TT * NB * KP0];   // (t, b, k)
__device__ __align__(16) __nv_bfloat16 g_xl[(size_t)TT * NB * KP0];
__device__ __align__(16) __nv_bfloat16 g_h0h[(size_t)TT * NB * KP1];  // (t, b, k)
__device__ __align__(16) __nv_bfloat16 g_h0l[(size_t)TT * NB * KP1];

// ---------------- helpers ----------------
__device__ __forceinline__ void ffma2(unsigned long long& acc,
                                      unsigned long long a, unsigned long long b) {
    asm("fma.rn.f32x2 %0, %1, %2, %0;" : "+l"(acc) : "l"(a), "l"(b));
}
__device__ __forceinline__ float2 unpk(unsigned long long v) {
    float2 r;
    asm("mov.b64 {%0, %1}, %2;" : "=f"(r.x), "=f"(r.y) : "l"(v));
    return r;
}
__device__ __forceinline__ float sigf(float x) { return 1.f / (1.f + __expf(-x)); }
__device__ __forceinline__ float tanhfast(float x) {
    float e = __expf(-2.f * x);
    return (1.f - e) * (1.f / (1.f + e));
}
__device__ __forceinline__ void bfsplit(float v, __nv_bfloat16& h, __nv_bfloat16& l) {
    h = __float2bfloat16(v);
    l = __float2bfloat16(v - __bfloat162float(h));
}
__device__ __forceinline__ uint32_t smem_u32(const void* p) {
    uint32_t a;
    asm("{ .reg .u64 t; cvta.to.shared.u64 t, %1; cvt.u32.u64 %0, t; }" : "=r"(a) : "l"(p));
    return a;
}

__device__ __forceinline__ void ldsm_x4(uint32_t addr, uint32_t r[4]) {
    asm volatile("ldmatrix.sync.aligned.m8n8.x4.shared.b16 {%0,%1,%2,%3}, [%4];"
        : "=r"(r[0]), "=r"(r[1]), "=r"(r[2]), "=r"(r[3]) : "r"(addr));
}
__device__ __forceinline__ void mma16816(float d[4], const uint32_t a[4],
                                         uint32_t b0, uint32_t b1) {
    asm volatile(
        "mma.sync.aligned.m16n8k16.row.col.f32.bf16.bf16.f32 "
        "{%0,%1,%2,%3}, {%4,%5,%6,%7}, {%8,%9}, {%0,%1,%2,%3};"
        : "+f"(d[0]), "+f"(d[1]), "+f"(d[2]), "+f"(d[3])
        : "r"(a[0]), "r"(a[1]), "r"(a[2]), "r"(a[3]), "r"(b0), "r"(b1));
}
__device__ __forceinline__ void cpasync16(uint32_t dst, const void* src) {
    asm volatile("cp.async.cg.shared.global [%0], [%1], 16;" :: "r"(dst), "l"(src));
}

// Sense-reversal grid barrier; requires all RCTAS CTAs co-resident.
__device__ __forceinline__ void grid_barrier() {
    __threadfence();
    __syncthreads();
    if (threadIdx.x == 0) {
        unsigned gen = atomicAdd(&g_barGen, 0u);
        unsigned a = atomicAdd(&g_barCnt, 1u);
        if (a == RCTAS - 1u) {
            atomicExch(&g_barCnt, 0u);
            __threadfence();
            atomicAdd(&g_barGen, 1u);
        } else {
            volatile unsigned* vg = &g_barGen;
            while (*vg == gen) { __nanosleep(64); }
        }
        __threadfence();
    }
    __syncthreads();
}

// ---------------- embedding -> bf16 hi/lo, (t, b, k) padded to KP0 ----------------
__global__ __launch_bounds__(256) void k_embsplit(const int* __restrict__ tokens,
                                                  const float* __restrict__ emb, int t0) {
    int t = t0 + blockIdx.x;
    __shared__ int stok[NB];
    if (threadIdx.x < NB) stok[threadIdx.x] = tokens[t * NB + threadIdx.x];
    __syncthreads();
    size_t base = (size_t)t * NB * KP0;
    for (int idx = threadIdx.x; idx < NB * KP0; idx += 256) {
        int b = idx / KP0, k = idx - b * KP0;
        float v = (k < 200) ? __ldg(&emb[(size_t)stok[b] * 200 + k]) : 0.f;
        __nv_bfloat16 h, l;
        bfsplit(v, h, l);
        g_xh[base + idx] = h;
        g_xl[base + idx] = l;
    }
}

// ---------------- ALL W -> bf16 hi/lo (merged: blockIdx.y selects weight) ----------------
__global__ __launch_bounds__(256) void k_wsplit_all(
    const float* __restrict__ w0f, const float* __restrict__ w0b,
    const float* __restrict__ w1f, const float* __restrict__ w1b)
{
    int sel = blockIdx.y;
    int layer = sel >> 1, dir = sel & 1;
    const float* w = (sel == 0) ? w0f : (sel == 1) ? w0b : (sel == 2) ? w1f : w1b;
    int K = layer ? 400 : 200;
    int KPv = layer ? KP1 : KP0;
    __nv_bfloat16* dh = (layer ? g_w1h : g_w0h) + (size_t)dir * 896 * KPv;
    __nv_bfloat16* dl = (layer ? g_w1l : g_w0l) + (size_t)dir * 896 * KPv;
    int idx = blockIdx.x * 256 + threadIdx.x;
    if (idx >= 896 * KPv) return;
    int m = idx / KPv, k = idx - m * KPv;
    float v = (m < 800 && k < K) ? __ldg(&w[(size_t)m * K + k]) : 0.f;
    __nv_bfloat16 h, l;
    bfsplit(v, h, l);
    dh[idx] = h;
    dl[idx] = l;
}

// ---------------- layer0 h (t,u,b) -> bf16 hi/lo (t,b,k) padded KP1 ----------------
__global__ __launch_bounds__(256) void k_h0split() {
    int t = blockIdx.x;
    __shared__ float ts[32][NB + 1];
    for (int c = 0; c < KP1 / 32; c++) {
        int u0 = c * 32;
        __syncthreads();
        for (int i = threadIdx.x; i < 32 * NB; i += 256) {
            int u = i >> 7, b = i & 127;
            ts[u][b] = (u0 + u < 400) ? g_h0[((size_t)t * 400 + u0 + u) * NB + b] : 0.f;
        }
        __syncthreads();
        for (int i = threadIdx.x; i < NB * 32; i += 256) {
            int b = i >> 5, u = i & 31;
            float v = ts[u][b];
            __nv_bfloat16 h, l;
            bfsplit(v, h, l);
            size_t o = ((size_t)t * NB + b) * KP1 + u0 + u;
            g_h0h[o] = h;
            g_h0l[o] = l;
        }
    }
}

// ---------------- tensor-core pre-GEMM (mma.sync bf16 hi/lo, 2-stage cp.async) -----
// D[m(128), b(128)] = sum_k W[m0+m][k] * X[t][b][k] + bias1[m] + bias2[m]
// grid (7 m-tiles, TT, 2 dirs), 256 thr = 8 warps (4m x 2n), warp tile 32x64.
// B stored [n][k] row-major => NON-trans ldmatrix yields the col-major B fragment.
#define MATSZ (128 * AP2)   // elems per matrix per stage
__global__ __launch_bounds__(256) void k_gemm_mma(
    int layer,
    const float* __restrict__ bih_f, const float* __restrict__ bhh_f,
    const float* __restrict__ bih_b, const float* __restrict__ bhh_b)
{
    __shared__ __align__(16) __nv_bfloat16 sm[2][4][MATSZ];   // 49152 B

    const int tid = threadIdx.x;
    const int warp = tid >> 5, lane = tid & 31;
    const int m0 = blockIdx.x * 128;
    const int t = blockIdx.y;
    const int dir = blockIdx.z;
    const int KPv = layer ? KP1 : KP0;
    const int nchunk = KPv / CH;
    const __nv_bfloat16* Ah = (layer ? g_w1h : g_w0h) + (size_t)dir * 896 * KPv + (size_t)m0 * KPv;
    const __nv_bfloat16* Al = (layer ? g_w1l : g_w0l) + (size_t)dir * 896 * KPv + (size_t)m0 * KPv;
    const __nv_bfloat16* Bh = (layer ? g_h0h : g_xh) + (size_t)t * NB * KPv;
    const __nv_bfloat16* Bl = (layer ? g_h0l : g_xl) + (size_t)t * NB * KPv;

    const int wm = (warp & 3) * 32;
    const int wn = (warp >> 2) * 64;
    const int lrow = lane & 15;
    const int lcol = (lane >> 4) * 8;

    const uint32_t sbase = smem_u32(sm);

    // staging decomposition: v = tid + j*256 in [0,1024): mat = v>>8, item = v&255
    // item -> row = item>>1, half = (item&1)*8 elems
    const int s_j0mat = tid >> 8;               // always 0; kept for clarity
    (void)s_j0mat;

    float acc[2][8][4];
#pragma unroll
    for (int i = 0; i < 2; i++)
#pragma unroll
        for (int n = 0; n < 8; n++)
#pragma unroll
            for (int q = 0; q < 4; q++) acc[i][n][q] = 0.f;

    // ---- prologue: stage chunk 0 into buffer 0
    {
        const int kb0 = 0;
#pragma unroll
        for (int j = 0; j < 4; j++) {
            int v = tid + j * 256;
            int mat = v >> 8;
            int item = v & 255;
            int row = item >> 1;
            int half = (item & 1) * 8;
            const __nv_bfloat16* src =
                ((mat == 0) ? Ah : (mat == 1) ? Al : (mat == 2) ? Bh : Bl)
                + (size_t)row * KPv + kb0 + half;
            uint32_t dst = sbase + (uint32_t)((0 * 4 + mat) * MATSZ + row * AP2 + half) * 2u;
            cpasync16(dst, src);
        }
        asm volatile("cp.async.commit_group;" ::: "memory");
    }

    for (int c = 0; c < nchunk; c++) {
        asm volatile("cp.async.wait_group 0;" ::: "memory");
        __syncthreads();

        // stage next chunk into the other buffer (its previous contents, chunk c-1,
        // are done: all warps passed the syncthreads above after computing c-1).
        if (c + 1 < nchunk) {
            const int kb0 = (c + 1) * CH;
            const int st = (c + 1) & 1;
#pragma unroll
            for (int j = 0; j < 4; j++) {
                int v = tid + j * 256;
                int mat = v >> 8;
                int item = v & 255;
                int row = item >> 1;
                int half = (item & 1) * 8;
                const __nv_bfloat16* src =
                    ((mat == 0) ? Ah : (mat == 1) ? Al : (mat == 2) ? Bh : Bl)
                    + (size_t)row * KPv + kb0 + half;
                uint32_t dst = sbase + (uint32_t)((st * 4 + mat) * MATSZ + row * AP2 + half) * 2u;
                cpasync16(dst, src);
            }
            asm volatile("cp.async.commit_group;" ::: "memory");
        }

        // ---- compute chunk c from buffer c&1 (one k16 step)
        {
            const int st = c & 1;
            const uint32_t bAh = sbase + (uint32_t)((st * 4 + 0) * MATSZ) * 2u;
            const uint32_t bAl = sbase + (uint32_t)((st * 4 + 1) * MATSZ) * 2u;
            const uint32_t bBh = sbase + (uint32_t)((st * 4 + 2) * MATSZ) * 2u;
            const uint32_t bBl = sbase + (uint32_t)((st * 4 + 3) * MATSZ) * 2u;

            uint32_t ah[2][4], al[2][4];
#pragma unroll
            for (int i = 0; i < 2; i++) {
                uint32_t off = (uint32_t)(((wm + i * 16 + lrow) * AP2 + lcol) * 2);
                ldsm_x4(bAh + off, ah[i]);
                ldsm_x4(bAl + off, al[i]);
            }
#pragma unroll
            for (int p = 0; p < 4; p++) {
                uint32_t off = (uint32_t)(((wn + p * 16 + lrow) * AP2 + lcol) * 2);
                uint32_t bh[4], bl[4];
                ldsm_x4(bBh + off, bh);
                ldsm_x4(bBl + off, bl);
#pragma unroll
                for (int i = 0; i < 2; i++) {
                    mma16816(acc[i][2 * p],     ah[i], bh[0], bh[2]);
                    mma16816(acc[i][2 * p + 1], ah[i], bh[1], bh[3]);
                    mma16816(acc[i][2 * p],     ah[i], bl[0], bl[2]);
                    mma16816(acc[i][2 * p + 1], ah[i], bl[1], bl[3]);
                    mma16816(acc[i][2 * p],     al[i], bh[0], bh[2]);
                    mma16816(acc[i][2 * p + 1], al[i], bh[1], bh[3]);
                }
            }
        }
    }

    // epilogue: bias + store fp32 (t, gate, b)
    const float* b1 = dir ? bih_b : bih_f;
    const float* b2 = dir ? bhh_b : bhh_f;
    float* outp = (dir ? g_pre_b : g_pre_f) + ((size_t)t * 800 + m0) * NB;
#pragma unroll
    for (int i = 0; i < 2; i++) {
#pragma unroll
        for (int half = 0; half < 2; half++) {
            int ml = wm + i * 16 + half * 8 + (lane >> 2);
            if (m0 + ml < 800) {
                float bs = __ldg(&b1[m0 + ml]) + __ldg(&b2[m0 + ml]);
                float* op = outp + (size_t)ml * NB + wn + (lane & 3) * 2;
#pragma unroll
                for (int n = 0; n < 8; n++) {
                    float2 v = make_float2(acc[i][n][half * 2] + bs,
                                           acc[i][n][half * 2 + 1] + bs);
                    *(float2*)(op + n * 8) = v;
                }
            }
        }
    }
}

// ---------------- persistent BiLSTM layer: 100 CTAs x 256 threads ----------------
// thread = (ty = unit-in-CTA 0..3, bx = 2 batch cols); gates + c state in registers.
__global__ __launch_bounds__(256) void k_recur(
    const float* __restrict__ whh_f, const float* __restrict__ whh_b, int layer)
{
    __shared__ __align__(16) float2 Wtp[200][16];  // [k][u*4+g], duplicated for f32x2
    __shared__ __align__(16) float Hs[2][KC][NB];

    const int tid = threadIdx.x;
    const int dir = blockIdx.x / 50;
    const int ub = (blockIdx.x % 50) * 4;
    const float* whh = dir ? whh_b : whh_f;
    const float* pre = dir ? g_pre_b : g_pre_f;
    float* hb0 = g_hbuf0 + dir * 200 * NB;
    float* hb1 = g_hbuf1 + dir * 200 * NB;

    for (int idx = tid; idx < 3200; idx += 256) {
        int r = idx & 15, k = idx >> 4;
        int u = r >> 2, g = r & 3;
        float w = whh[(size_t)(g * 200 + ub + u) * 200 + k];
        Wtp[k][r] = make_float2(w, w);
    }

    const int ty = tid >> 6;        // unit in CTA (0..3)
    const int bx = (tid & 63) * 2;  // batch cols bx, bx+1

    float cc[2] = {0.f, 0.f};
    *(float2*)&hb0[(ub + ty) * NB + bx] = make_float2(0.f, 0.f);
    grid_barrier();

    for (int s = 0; s < TT; s++) {
        const int t = dir ? (TT - 1 - s) : s;
        const float* hprev = (s & 1) ? hb1 : hb0;
        float* hnext = (s & 1) ? hb0 : hb1;
        const float* pt = pre + (size_t)t * 800 * NB;

        float2 pv[4];
#pragma unroll
        for (int g = 0; g < 4; g++)
            pv[g] = *(const float2*)&pt[(size_t)(g * 200 + ub + ty) * NB + bx];

        unsigned long long acc[4] = {0ull, 0ull, 0ull, 0ull};

        float4 pr[5];
        if (tid < 128) {
#pragma unroll
            for (int i = 0; i < 5; i++) {
                int idx = tid + i * 128;
                pr[i] = __ldcg((const float4*)&hprev[(idx >> 5) * NB + (idx & 31) * 4]);
            }
#pragma unroll
            for (int i = 0; i < 5; i++) {
                int idx = tid + i * 128;
                *(float4*)&Hs[0][idx >> 5][(idx & 31) * 4] = pr[i];
            }
        }
        __syncthreads();

        for (int kc = 0; kc < 10; kc++) {
            const int cur = kc & 1;
            if (tid < 128 && kc < 9) {
#pragma unroll
                for (int i = 0; i < 5; i++) {
                    int idx = tid + i * 128;
                    pr[i] = __ldcg((const float4*)&hprev[((kc + 1) * KC + (idx >> 5)) * NB + (idx & 31) * 4]);
                }
            }
#pragma unroll 5
            for (int kk = 0; kk < KC; kk++) {
                ulonglong2 w01 = *(const ulonglong2*)&Wtp[kc * KC + kk][ty * 4];
                ulonglong2 w23 = *(const ulonglong2*)&Wtp[kc * KC + kk][ty * 4 + 2];
                unsigned long long h = *(const unsigned long long*)&Hs[cur][kk][bx];
                ffma2(acc[0], w01.x, h);
                ffma2(acc[1], w01.y, h);
                ffma2(acc[2], w23.x, h);
                ffma2(acc[3], w23.y, h);
            }
            if (tid < 128 && kc < 9) {
#pragma unroll
                for (int i = 0; i < 5; i++) {
                    int idx = tid + i * 128;
                    *(float4*)&Hs[cur ^ 1][idx >> 5][(idx & 31) * 4] = pr[i];
                }
            }
            __syncthreads();
        }

        float gv[4][2];
#pragma unroll
        for (int g = 0; g < 4; g++) {
            float2 a = unpk(acc[g]);
            gv[g][0] = a.x + pv[g].x;
            gv[g][1] = a.y + pv[g].y;
        }
        float hv[2];
#pragma unroll
        for (int j = 0; j < 2; j++) {
            float iv = sigf(gv[0][j]);
            float fv = sigf(gv[1][j]);
            float gg = tanhfast(gv[2][j]);
            float ov = sigf(gv[3][j]);
            float c = fv * cc[j] + iv * gg;
            cc[j] = c;
            hv[j] = ov * tanhfast(c);
        }
        *(float2*)&hnext[(ub + ty) * NB + bx] = make_float2(hv[0], hv[1]);
        if (layer == 0) {
            *(float2*)&g_h0[((size_t)t * 400 + dir * 200 + ub + ty) * NB + bx] =
                make_float2(hv[0], hv[1]);
        } else {
#pragma unroll
            for (int j = 0; j < 2; j++)
                g_hbt[((size_t)(bx + j) * TT + t) * 400 + dir * 200 + ub + ty] = hv[j];
        }
        grid_barrier();
    }
}

// ---------------- fused path-gather + MLP1 (tanh) ----------------
__global__ __launch_bounds__(256) void k_gather_mlp1(
    const int* __restrict__ paths, const float* __restrict__ w1, const float* __restrict__ b1)
{
    __shared__ __align__(16) float As[8][128];
    __shared__ __align__(16) float Bs[8][64];
    __shared__ long long abase[128][2];
    const int tid = threadIdx.x;
    const int s0 = blockIdx.x * 128;
    const int n0 = blockIdx.y * 64;

    {
        int i = tid >> 1, j = tid & 1;
        int s = s0 + i;
        int tval = paths[(size_t)s * 2 + j];
        int b = s >> 8;
        abase[i][j] = (tval >= 0) ? ((long long)b * TT + tval) * 400LL : -1LL;
    }
    __syncthreads();

    const int la_i = tid >> 1;
    const int la_k = (tid & 1) * 4;
    const int lb_n = tid >> 2;
    const int lb_k = (tid & 3) * 2;
    const int tm = (tid >> 4) * 8;
    const int tn = (tid & 15) * 4;

    float acc[8][4];
#pragma unroll
    for (int i = 0; i < 8; i++)
#pragma unroll
        for (int j = 0; j < 4; j++) acc[i][j] = 0.f;

    for (int k0 = 0; k0 < 800; k0 += 8) {
        int k = k0 + la_k;
        int j = (k >= 400) ? 1 : 0;
        int u = k - j * 400;
        long long base = abase[la_i][j];
        float4 av = make_float4(0.f, 0.f, 0.f, 0.f);
        if (base >= 0) av = *(const float4*)&g_hbt[base + u];
        float2 bv = make_float2(0.f, 0.f);
        int n = n0 + lb_n;
        if (n < 200) bv = *(const float2*)&w1[(size_t)n * 800 + k0 + lb_k];
        __syncthreads();
        As[la_k][la_i] = av.x;
        As[la_k + 1][la_i] = av.y;
        As[la_k + 2][la_i] = av.z;
        As[la_k + 3][la_i] = av.w;
        Bs[lb_k][lb_n] = bv.x;
        Bs[lb_k + 1][lb_n] = bv.y;
        __syncthreads();
#pragma unroll
        for (int kk = 0; kk < 8; kk++) {
            float4 a0 = *(float4*)&As[kk][tm];
            float4 a1 = *(float4*)&As[kk][tm + 4];
            float4 b4 = *(float4*)&Bs[kk][tn];
            float avv[8] = {a0.x, a0.y, a0.z, a0.w, a1.x, a1.y, a1.z, a1.w};
            float bvv[4] = {b4.x, b4.y, b4.z, b4.w};
#pragma unroll
            for (int i = 0; i < 8; i++)
#pragma unroll
                for (int j2 = 0; j2 < 4; j2++) acc[i][j2] += avv[i] * bvv[j2];
        }
    }
#pragma unroll
    for (int r = 0; r < 8; r++) {
        int s = s0 + tm + r;
        float4 ov;
        float* po = &ov.x;
#pragma unroll
        for (int c2 = 0; c2 < 4; c2++) {
            int n = n0 + tn + c2;
            po[c2] = (n < 200) ? tanhf(acc[r][c2] + __ldg(&b1[n])) : 0.f;
        }
        if (n0 + tn < 200)
            *(float4*)&g_hid[(size_t)s * 200 + n0 + tn] = ov;
    }
}

// ---------------- MLP2 + softmax: one warp per sample ----------------
__global__ __launch_bounds__(128) void k_mlp2(
    const float* __restrict__ w2, const float* __restrict__ b2, float* __restrict__ out)
{
    __shared__ float w2s[800];
    __shared__ float b2s[4];
    const int tid = threadIdx.x;
    for (int i = tid; i < 800; i += 128) w2s[i] = w2[i];
    if (tid < 4) b2s[tid] = b2[tid];
    __syncthreads();
    const int warp = tid >> 5, lane = tid & 31;
    const int s = blockIdx.x * 4 + warp;
    const float* hr = g_hid + (size_t)s * 200;
    float a0 = 0.f, a1 = 0.f, a2 = 0.f, a3 = 0.f;
    for (int k = lane; k < 200; k += 32) {
        float h = hr[k];
        a0 += h * w2s[k];
        a1 += h * w2s[200 + k];
        a2 += h * w2s[400 + k];
        a3 += h * w2s[600 + k];
    }
#pragma unroll
    for (int o = 16; o > 0; o >>= 1) {
        a0 += __shfl_down_sync(0xffffffffu, a0, o);
        a1 += __shfl_down_sync(0xffffffffu, a1, o);
        a2 += __shfl_down_sync(0xffffffffu, a2, o);
        a3 += __shfl_down_sync(0xffffffffu, a3, o);
    }
    if (lane == 0) {
        float l0 = a0 + b2s[0], l1 = a1 + b2s[1], l2 = a2 + b2s[2], l3 = a3 + b2s[3];
        float m = fmaxf(fmaxf(l0, l1), fmaxf(l2, l3));
        float e0 = expf(l0 - m), e1 = expf(l1 - m), e2 = expf(l2 - m), e3 = expf(l3 - m);
        float inv = 1.f / (e0 + e1 + e2 + e3);
        float4 r = make_float4(e0 * inv, e1 * inv, e2 * inv, e3 * inv);
        *(float4*)&out[(size_t)s * 4] = r;
    }
}

extern "C" void kernel_launch(void* const* d_in, const int* in_sizes, int n_in,
                              void* d_out, int out_size)
{
    const int* tokens = (const int*)d_in[0];
    const int* paths = (const int*)d_in[1];
    const float* emb = (const float*)d_in[2];
    const float* wih0f = (const float*)d_in[3];
    const float* whh0f = (const float*)d_in[4];
    const float* bih0f = (const float*)d_in[5];
    const float* bhh0f = (const float*)d_in[6];
    const float* wih0b = (const float*)d_in[7];
    const float* whh0b = (const float*)d_in[8];
    const float* bih0b = (const float*)d_in[9];
    const float* bhh0b = (const float*)d_in[10];
    const float* wih1f = (const float*)d_in[11];
    const float* whh1f = (const float*)d_in[12];
    const float* bih1f = (const float*)d_in[13];
    const float* bhh1f = (const float*)d_in[14];
    const float* wih1b = (const float*)d_in[15];
    const float* whh1b = (const float*)d_in[16];
    const float* bih1b = (const float*)d_in[17];
    const float* bhh1b = (const float*)d_in[18];
    const float* w1 = (const float*)d_in[19];
    const float* b1 = (const float*)d_in[20];
    const float* w2 = (const float*)d_in[21];
    const float* b2 = (const float*)d_in[22];
    float* out = (float*)d_out;

    // prep (3 launches so that launch #4 = k_gemm_mma layer0 -> gets ncu-captured)
    k_embsplit<<<TT / 2, 256>>>(tokens, emb, 0);         // launch 1
    k_embsplit<<<TT / 2, 256>>>(tokens, emb, TT / 2);    // launch 2
    int nbx = (896 * KP1 + 255) / 256;
    dim3 gw(nbx, 4);
    k_wsplit_all<<<gw, 256>>>(wih0f, wih0b, wih1f, wih1b); // launch 3

    dim3 gg(7, TT, 2);
    k_gemm_mma<<<gg, 256>>>(0, bih0f, bhh0f, bih0b, bhh0b); // launch 4 (profiled)
    k_recur<<<RCTAS, 256>>>(whh0f, whh0b, 0);
    k_h0split<<<TT, 256>>>();
    k_gemm_mma<<<gg, 256>>>(1, bih1f, bhh1f, bih1b, bhh1b);
    k_recur<<<RCTAS, 256>>>(whh1f, whh1b, 1);

    dim3 g4(NSAMP / 128, 4);
    k_gather_mlp1<<<g4, 256>>>(paths, w1, b1);
    k_mlp2<<<NSAMP / 4, 128>>>(w2, b2, out);
}

// round 8
// speedup vs baseline: 1.3627x; 1.3627x over previous
#include <cuda_runtime.h>
#include <cuda_bf16.h>
#include <cstdint>

#define TT 512
#define NB 128
#define NSAMP 32768
#define KP0 224
#define KP1 416
#define AP 40    // GEMM smem stride (bf16) for 32-wide k chunks
#define RCN 50   // recurrence CTAs (25 per direction)
#define KR 208   // recurrence padded K (13 x k16)
#define SK 216   // recurrence smem row stride (bf16 elems), conflict-free ldmatrix

// ---------------- static scratch (no allocation; zero-initialized at load) -------
__device__ float g_pre_f[(size_t)TT * 800 * NB];   // (t, gate, b)
__device__ float g_pre_b[(size_t)TT * 800 * NB];
__device__ float g_hbt[(size_t)NB * TT * 400];     // layer1 out (b, t, u) fp32
__device__ float g_hid[(size_t)NSAMP * 200];       // MLP hidden (s, n)
__device__ unsigned g_barCnt;
__device__ unsigned g_barGen;

// bf16-split operand buffers (hi + lo)
__device__ __align__(16) __nv_bfloat16 g_w0h[(size_t)2 * 896 * KP0];  // [dir][m][k]
__device__ __align__(16) __nv_bfloat16 g_w0l[(size_t)2 * 896 * KP0];
__device__ __align__(16) __nv_bfloat16 g_w1h[(size_t)2 * 896 * KP1];
__device__ __align__(16) __nv_bfloat16 g_w1l[(size_t)2 * 896 * KP1];
__device__ __align__(16) __nv_bfloat16 g_xh[(size_t)TT * NB * KP0];   // (t, b, k)
__device__ __align__(16) __nv_bfloat16 g_xl[(size_t)TT * NB * KP0];
__device__ __align__(16) __nv_bfloat16 g_h0h[(size_t)TT * NB * KP1];  // layer0 out (t,b,k)
__device__ __align__(16) __nv_bfloat16 g_h0l[(size_t)TT * NB * KP1];
// recurrence weights, interleaved rows (u*4+g), [layer][dir][800][KR]
__device__ __align__(16) __nv_bfloat16 g_wrh[(size_t)2 * 2 * 800 * KR];
__device__ __align__(16) __nv_bfloat16 g_wrl[(size_t)2 * 2 * 800 * KR];
// recurrent h ping-pong, [dir][buf][b][SK] (k pad >=200 stays zero forever)
__device__ __align__(16) __nv_bfloat16 g_hh[(size_t)2 * 2 * NB * SK];
__device__ __align__(16) __nv_bfloat16 g_hl[(size_t)2 * 2 * NB * SK];

// ---------------- helpers ----------------
__device__ __forceinline__ float sigf(float x) { return 1.f / (1.f + __expf(-x)); }
__device__ __forceinline__ float tanhfast(float x) {
    float e = __expf(-2.f * x);
    return (1.f - e) * (1.f / (1.f + e));
}
__device__ __forceinline__ void bfsplit(float v, __nv_bfloat16& h, __nv_bfloat16& l) {
    h = __float2bfloat16(v);
    l = __float2bfloat16(v - __bfloat162float(h));
}
__device__ __forceinline__ uint32_t smem_u32(const void* p) {
    uint32_t a;
    asm("{ .reg .u64 t; cvta.to.shared.u64 t, %1; cvt.u32.u64 %0, t; }" : "=r"(a) : "l"(p));
    return a;
}
__device__ __forceinline__ void ldsm_x4(uint32_t addr, uint32_t r[4]) {
    asm volatile("ldmatrix.sync.aligned.m8n8.x4.shared.b16 {%0,%1,%2,%3}, [%4];"
        : "=r"(r[0]), "=r"(r[1]), "=r"(r[2]), "=r"(r[3]) : "r"(addr));
}
__device__ __forceinline__ void mma16816(float d[4], const uint32_t a[4],
                                         uint32_t b0, uint32_t b1) {
    asm volatile(
        "mma.sync.aligned.m16n8k16.row.col.f32.bf16.bf16.f32 "
        "{%0,%1,%2,%3}, {%4,%5,%6,%7}, {%8,%9}, {%0,%1,%2,%3};"
        : "+f"(d[0]), "+f"(d[1]), "+f"(d[2]), "+f"(d[3])
        : "r"(a[0]), "r"(a[1]), "r"(a[2]), "r"(a[3]), "r"(b0), "r"(b1));
}
__device__ __forceinline__ void cpasync16(uint32_t dst, const void* src) {
    asm volatile("cp.async.cg.shared.global [%0], [%1], 16;" :: "r"(dst), "l"(src));
}
__device__ __forceinline__ uint32_t pack_bf2(__nv_bfloat16 a, __nv_bfloat16 b) {
    return (uint32_t)__bfloat16_as_ushort(a) | ((uint32_t)__bfloat16_as_ushort(b) << 16);
}

// Sense-reversal grid barrier; requires all RCN CTAs co-resident.
__device__ __forceinline__ void grid_barrier() {
    __threadfence();
    __syncthreads();
    if (threadIdx.x == 0) {
        unsigned gen = atomicAdd(&g_barGen, 0u);
        unsigned a = atomicAdd(&g_barCnt, 1u);
        if (a == RCN - 1u) {
            atomicExch(&g_barCnt, 0u);
            __threadfence();
            atomicAdd(&g_barGen, 1u);
        } else {
            volatile unsigned* vg = &g_barGen;
            while (*vg == gen) { __nanosleep(64); }
        }
        __threadfence();
    }
    __syncthreads();
}

// ---------------- embedding -> bf16 hi/lo, (t, b, k) padded to KP0 ----------------
__global__ __launch_bounds__(256) void k_embsplit(const int* __restrict__ tokens,
                                                  const float* __restrict__ emb) {
    int t = blockIdx.x;
    __shared__ int stok[NB];
    if (threadIdx.x < NB) stok[threadIdx.x] = tokens[t * NB + threadIdx.x];
    __syncthreads();
    size_t base = (size_t)t * NB * KP0;
    for (int idx = threadIdx.x; idx < NB * KP0; idx += 256) {
        int b = idx / KP0, k = idx - b * KP0;
        float v = (k < 200) ? __ldg(&emb[(size_t)stok[b] * 200 + k]) : 0.f;
        __nv_bfloat16 h, l;
        bfsplit(v, h, l);
        g_xh[base + idx] = h;
        g_xl[base + idx] = l;
    }
}

// ---------------- ALL weight prep: input W splits (sel 0-3) + rec W packs (sel 4-7)
__global__ __launch_bounds__(256) void k_prepw(
    const float* __restrict__ w0f, const float* __restrict__ w0b,
    const float* __restrict__ w1f, const float* __restrict__ w1b,
    const float* __restrict__ r0f, const float* __restrict__ r0b,
    const float* __restrict__ r1f, const float* __restrict__ r1b)
{
    int sel = blockIdx.y;
    int idx = blockIdx.x * 256 + threadIdx.x;
    if (sel < 4) {
        int layer = sel >> 1, dirv = sel & 1;
        const float* w = (sel == 0) ? w0f : (sel == 1) ? w0b : (sel == 2) ? w1f : w1b;
        int K = layer ? 400 : 200;
        int KPv = layer ? KP1 : KP0;
        if (idx >= 896 * KPv) return;
        __nv_bfloat16* dh = (layer ? g_w1h : g_w0h) + (size_t)dirv * 896 * KPv;
        __nv_bfloat16* dl = (layer ? g_w1l : g_w0l) + (size_t)dirv * 896 * KPv;
        int m = idx / KPv, k = idx - m * KPv;
        float v = (m < 800 && k < K) ? __ldg(&w[(size_t)m * K + k]) : 0.f;
        __nv_bfloat16 h, l;
        bfsplit(v, h, l);
        dh[idx] = h;
        dl[idx] = l;
    } else {
        int layer = (sel - 4) >> 1, dirv = (sel - 4) & 1;
        const float* w = (sel == 4) ? r0f : (sel == 5) ? r0b : (sel == 6) ? r1f : r1b;
        if (idx >= 800 * KR) return;
        int r = idx / KR, k = idx - r * KR;
        int u = r >> 2, g = r & 3;
        float v = (k < 200) ? __ldg(&w[(size_t)(g * 200 + u) * 200 + k]) : 0.f;
        __nv_bfloat16 h, l;
        bfsplit(v, h, l);
        size_t o = ((size_t)(layer * 2 + dirv) * 800 + r) * KR + k;
        g_wrh[o] = h;
        g_wrl[o] = l;
    }
}

// ---------------- tensor-core pre-GEMM (round-6 proven version) ----------------
__global__ __launch_bounds__(256) void k_gemm_mma(
    int layer,
    const float* __restrict__ bih_f, const float* __restrict__ bhh_f,
    const float* __restrict__ bih_b, const float* __restrict__ bhh_b)
{
    __shared__ __align__(16) __nv_bfloat16 sAh[128 * AP], sAl[128 * AP];
    __shared__ __align__(16) __nv_bfloat16 sBh[128 * AP], sBl[128 * AP];

    const int tid = threadIdx.x;
    const int warp = tid >> 5, lane = tid & 31;
    const int m0 = blockIdx.x * 128;
    const int t = blockIdx.y;
    const int dir = blockIdx.z;
    const int KPv = layer ? KP1 : KP0;
    const int nchunk = KPv >> 5;
    const __nv_bfloat16* Ah = (layer ? g_w1h : g_w0h) + (size_t)dir * 896 * KPv + (size_t)m0 * KPv;
    const __nv_bfloat16* Al = (layer ? g_w1l : g_w0l) + (size_t)dir * 896 * KPv + (size_t)m0 * KPv;
    const __nv_bfloat16* Bh = (layer ? g_h0h : g_xh) + (size_t)t * NB * KPv;
    const __nv_bfloat16* Bl = (layer ? g_h0l : g_xl) + (size_t)t * NB * KPv;

    const int wm = (warp & 3) * 32;
    const int wn = (warp >> 2) * 64;
    const int lrow = lane & 15;
    const int lcol = (lane >> 4) * 8;

    const uint32_t aAh = smem_u32(sAh), aAl = smem_u32(sAl);
    const uint32_t aBh = smem_u32(sBh), aBl = smem_u32(sBl);

    float acc[2][8][4];
#pragma unroll
    for (int i = 0; i < 2; i++)
#pragma unroll
        for (int n = 0; n < 8; n++)
#pragma unroll
            for (int q = 0; q < 4; q++) acc[i][n][q] = 0.f;

    const int srow = tid >> 2;
    const int skv = (tid & 3) * 8;

    for (int c = 0; c < nchunk; c++) {
        const int kb0 = c * 32;
#pragma unroll
        for (int jv = 0; jv < 2; jv++) {
            int row = srow + jv * 64;
            size_t go = (size_t)row * KPv + kb0 + skv;
            int so = row * AP + skv;
            *(uint4*)&sAh[so] = *(const uint4*)(Ah + go);
            *(uint4*)&sAl[so] = *(const uint4*)(Al + go);
            *(uint4*)&sBh[so] = *(const uint4*)(Bh + go);
            *(uint4*)&sBl[so] = *(const uint4*)(Bl + go);
        }
        __syncthreads();
#pragma unroll
        for (int ks = 0; ks < 2; ks++) {
            const int kb = ks * 16;
            uint32_t ah[2][4], al[2][4];
#pragma unroll
            for (int i = 0; i < 2; i++) {
                uint32_t off = (uint32_t)(((wm + i * 16 + lrow) * AP + kb + lcol) * 2);
                ldsm_x4(aAh + off, ah[i]);
                ldsm_x4(aAl + off, al[i]);
            }
#pragma unroll
            for (int p = 0; p < 4; p++) {
                uint32_t off = (uint32_t)(((wn + p * 16 + lrow) * AP + kb + lcol) * 2);
                uint32_t bh[4], bl[4];
                ldsm_x4(aBh + off, bh);
                ldsm_x4(aBl + off, bl);
#pragma unroll
                for (int i = 0; i < 2; i++) {
                    mma16816(acc[i][2 * p],     ah[i], bh[0], bh[2]);
                    mma16816(acc[i][2 * p + 1], ah[i], bh[1], bh[3]);
                    mma16816(acc[i][2 * p],     ah[i], bl[0], bl[2]);
                    mma16816(acc[i][2 * p + 1], ah[i], bl[1], bl[3]);
                    mma16816(acc[i][2 * p],     al[i], bh[0], bh[2]);
                    mma16816(acc[i][2 * p + 1], al[i], bh[1], bh[3]);
                }
            }
        }
        __syncthreads();
    }

    const float* b1 = dir ? bih_b : bih_f;
    const float* b2 = dir ? bhh_b : bhh_f;
    float* outp = (dir ? g_pre_b : g_pre_f) + ((size_t)t * 800 + m0) * NB;
#pragma unroll
    for (int i = 0; i < 2; i++) {
#pragma unroll
        for (int half = 0; half < 2; half++) {
            int ml = wm + i * 16 + half * 8 + (lane >> 2);
            if (m0 + ml < 800) {
                float bs = __ldg(&b1[m0 + ml]) + __ldg(&b2[m0 + ml]);
                float* op = outp + (size_t)ml * NB + wn + (lane & 3) * 2;
#pragma unroll
                for (int n = 0; n < 8; n++) {
                    float2 v = make_float2(acc[i][n][half * 2] + bs,
                                           acc[i][n][half * 2 + 1] + bs);
                    *(float2*)(op + n * 8) = v;
                }
            }
        }
    }
}

// ---------------- persistent MMA recurrence: 50 CTAs (25/dir, 8 units each) -----
// Dynamic smem layout (bytes):
//   0      hH  [128][SK] bf16  (55296)
//   55296  hL                  (55296)
//   110592 wH  [32][SK] bf16   (13824)
//   124416 wL                  (13824)
//   138240 D   [32][128] f32   (16384)
//   154624 hsm [128][8]  f32   (4096)
#define RSMEM 158720
__global__ __launch_bounds__(256) void k_recur_mma(int layer)
{
    extern __shared__ __align__(16) char dsm[];
    const uint32_t sb = smem_u32(dsm);
    const uint32_t sHH = sb;
    const uint32_t sHL = sb + 55296;
    const uint32_t sWH = sb + 110592;
    const uint32_t sWL = sb + 124416;
    float* Dsm = (float*)(dsm + 138240);
    float* hsm = (float*)(dsm + 154624);

    const int tid = threadIdx.x;
    const int warp = tid >> 5, lane = tid & 31;
    const int dir = blockIdx.x / 25;
    const int cu = blockIdx.x % 25;
    const int u0 = cu * 8;
    const int row0 = cu * 32;
    const int lrow = lane & 15, lcol = (lane >> 4) * 8;
    const int wm = (warp & 1) * 16;
    const int wn = (warp >> 1) * 32;

    const __nv_bfloat16* wrh = g_wrh + ((size_t)(layer * 2 + dir) * 800 + row0) * KR;
    const __nv_bfloat16* wrl = g_wrl + ((size_t)(layer * 2 + dir) * 800 + row0) * KR;
    const float* pre = dir ? g_pre_b : g_pre_f;

    // stage Wrec (32 rows x 208) into smem, stride SK
    for (int i = tid; i < 832; i += 256) {
        int r = i / 26, seg = i - r * 26;
        uint32_t d = (uint32_t)((r * SK + seg * 8) * 2);
        cpasync16(sWH + d, wrh + (size_t)r * KR + seg * 8);
        cpasync16(sWL + d, wrl + (size_t)r * KR + seg * 8);
    }
    asm volatile("cp.async.commit_group;" ::: "memory");

    // zero h buf0 own slice (graph replays reuse buffers!)
    {
        int b = tid >> 1, half = tid & 1;
        size_t o = ((size_t)(dir * 2 + 0) * NB + b) * SK + u0 + half * 4;
        *(uint2*)&g_hh[o] = make_uint2(0u, 0u);
        *(uint2*)&g_hl[o] = make_uint2(0u, 0u);
    }
    float cc[2][2] = {{0.f, 0.f}, {0.f, 0.f}};
    asm volatile("cp.async.wait_group 0;" ::: "memory");
    grid_barrier();

    const int j0 = tid >> 6;          // gate-phase unit base (0..3)
    const int cp2 = (tid & 63) * 2;   // gate-phase batch col

    for (int s = 0; s < TT; s++) {
        const int t = dir ? (TT - 1 - s) : s;
        const int pb = s & 1;

        // prefetch full h (128 x 208, hi+lo) into smem; cp.async bypasses L1
        const size_t hb = (size_t)(dir * 2 + pb) * NB * SK;
        for (int i = tid; i < 3328; i += 256) {
            int r = i / 26, seg = i - r * 26;
            uint32_t d = (uint32_t)((r * SK + seg * 8) * 2);
            cpasync16(sHH + d, g_hh + hb + (size_t)r * SK + seg * 8);
            cpasync16(sHL + d, g_hl + hb + (size_t)r * SK + seg * 8);
        }
        asm volatile("cp.async.commit_group;" ::: "memory");

        // pre-activations for this thread's gate items (L1 path, overlaps cp.async)
        float2 pv[2][4];
        const float* pt = pre + (size_t)t * 800 * NB;
#pragma unroll
        for (int jj = 0; jj < 2; jj++) {
            int u = u0 + j0 + jj * 4;
#pragma unroll
            for (int g = 0; g < 4; g++)
                pv[jj][g] = *(const float2*)&pt[(size_t)(g * 200 + u) * NB + cp2];
        }

        asm volatile("cp.async.wait_group 0;" ::: "memory");
        __syncthreads();

        // D(32x128) = Wrec @ h  (bf16 hi/lo split, 3 MMAs per fragment)
        float acc[4][4];
#pragma unroll
        for (int i = 0; i < 4; i++)
#pragma unroll
            for (int q = 0; q < 4; q++) acc[i][q] = 0.f;
#pragma unroll
        for (int ch = 0; ch < 13; ch++) {
            const int ko = ch * 16;
            uint32_t aH[4], aL[4];
            uint32_t offA = (uint32_t)(((wm + lrow) * SK + ko + lcol) * 2);
            ldsm_x4(sWH + offA, aH);
            ldsm_x4(sWL + offA, aL);
#pragma unroll
            for (int p = 0; p < 2; p++) {
                uint32_t offB = (uint32_t)(((wn + p * 16 + lrow) * SK + ko + lcol) * 2);
                uint32_t bh[4], bl[4];
                ldsm_x4(sHH + offB, bh);
                ldsm_x4(sHL + offB, bl);
                mma16816(acc[2 * p],     aH, bh[0], bh[2]);
                mma16816(acc[2 * p + 1], aH, bh[1], bh[3]);
                mma16816(acc[2 * p],     aH, bl[0], bl[2]);
                mma16816(acc[2 * p + 1], aH, bl[1], bl[3]);
                mma16816(acc[2 * p],     aL, bh[0], bh[2]);
                mma16816(acc[2 * p + 1], aL, bh[1], bh[3]);
            }
        }
        // D -> smem
#pragma unroll
        for (int n = 0; n < 4; n++) {
            int col = wn + n * 8 + (lane & 3) * 2;
            int r0r = wm + (lane >> 2);
            *(float2*)&Dsm[r0r * 128 + col] = make_float2(acc[n][0], acc[n][1]);
            *(float2*)&Dsm[(r0r + 8) * 128 + col] = make_float2(acc[n][2], acc[n][3]);
        }
        __syncthreads();

        // gates: thread handles units {j0, j0+4} x cols {cp2, cp2+1}
#pragma unroll
        for (int jj = 0; jj < 2; jj++) {
            int j = j0 + jj * 4;
            float2 gi = *(float2*)&Dsm[(j * 4 + 0) * 128 + cp2];
            float2 gf = *(float2*)&Dsm[(j * 4 + 1) * 128 + cp2];
            float2 gg = *(float2*)&Dsm[(j * 4 + 2) * 128 + cp2];
            float2 go = *(float2*)&Dsm[(j * 4 + 3) * 128 + cp2];
            gi.x += pv[jj][0].x; gi.y += pv[jj][0].y;
            gf.x += pv[jj][1].x; gf.y += pv[jj][1].y;
            gg.x += pv[jj][2].x; gg.y += pv[jj][2].y;
            go.x += pv[jj][3].x; go.y += pv[jj][3].y;
            float c0 = sigf(gf.x) * cc[jj][0] + sigf(gi.x) * tanhfast(gg.x);
            float c1 = sigf(gf.y) * cc[jj][1] + sigf(gi.y) * tanhfast(gg.y);
            cc[jj][0] = c0; cc[jj][1] = c1;
            hsm[cp2 * 8 + j] = sigf(go.x) * tanhfast(c0);
            hsm[(cp2 + 1) * 8 + j] = sigf(go.y) * tanhfast(c1);
        }
        __syncthreads();

        // write-out: thread (b, half) handles 4 units
        {
            int b = tid >> 1, half = tid & 1;
            float4 hv = *(float4*)&hsm[b * 8 + half * 4];
            __nv_bfloat16 h0, l0, h1, l1, h2, l2, h3, l3;
            bfsplit(hv.x, h0, l0); bfsplit(hv.y, h1, l1);
            bfsplit(hv.z, h2, l2); bfsplit(hv.w, h3, l3);
            uint2 ph = make_uint2(pack_bf2(h0, h1), pack_bf2(h2, h3));
            uint2 pl = make_uint2(pack_bf2(l0, l1), pack_bf2(l2, l3));
            size_t o = ((size_t)(dir * 2 + (pb ^ 1)) * NB + b) * SK + u0 + half * 4;
            *(uint2*)&g_hh[o] = ph;
            *(uint2*)&g_hl[o] = pl;
            if (layer == 0) {
                size_t o2 = ((size_t)t * NB + b) * KP1 + dir * 200 + u0 + half * 4;
                *(uint2*)&g_h0h[o2] = ph;
                *(uint2*)&g_h0l[o2] = pl;
            } else {
                size_t o3 = ((size_t)b * TT + t) * 400 + dir * 200 + u0 + half * 4;
                *(float4*)&g_hbt[o3] = hv;
            }
        }
        grid_barrier();
    }
}

// ---------------- fused path-gather + MLP1 (tanh) ----------------
__global__ __launch_bounds__(256) void k_gather_mlp1(
    const int* __restrict__ paths, const float* __restrict__ w1, const float* __restrict__ b1)
{
    __shared__ __align__(16) float As[8][128];
    __shared__ __align__(16) float Bs[8][64];
    __shared__ long long abase[128][2];
    const int tid = threadIdx.x;
    const int s0 = blockIdx.x * 128;
    const int n0 = blockIdx.y * 64;

    {
        int i = tid >> 1, j = tid & 1;
        int s = s0 + i;
        int tval = paths[(size_t)s * 2 + j];
        int b = s >> 8;
        abase[i][j] = (tval >= 0) ? ((long long)b * TT + tval) * 400LL : -1LL;
    }
    __syncthreads();

    const int la_i = tid >> 1;
    const int la_k = (tid & 1) * 4;
    const int lb_n = tid >> 2;
    const int lb_k = (tid & 3) * 2;
    const int tm = (tid >> 4) * 8;
    const int tn = (tid & 15) * 4;

    float acc[8][4];
#pragma unroll
    for (int i = 0; i < 8; i++)
#pragma unroll
        for (int j = 0; j < 4; j++) acc[i][j] = 0.f;

    for (int k0 = 0; k0 < 800; k0 += 8) {
        int k = k0 + la_k;
        int j = (k >= 400) ? 1 : 0;
        int u = k - j * 400;
        long long base = abase[la_i][j];
        float4 av = make_float4(0.f, 0.f, 0.f, 0.f);
        if (base >= 0) av = *(const float4*)&g_hbt[base + u];
        float2 bv = make_float2(0.f, 0.f);
        int n = n0 + lb_n;
        if (n < 200) bv = *(const float2*)&w1[(size_t)n * 800 + k0 + lb_k];
        __syncthreads();
        As[la_k][la_i] = av.x;
        As[la_k + 1][la_i] = av.y;
        As[la_k + 2][la_i] = av.z;
        As[la_k + 3][la_i] = av.w;
        Bs[lb_k][lb_n] = bv.x;
        Bs[lb_k + 1][lb_n] = bv.y;
        __syncthreads();
#pragma unroll
        for (int kk = 0; kk < 8; kk++) {
            float4 a0 = *(float4*)&As[kk][tm];
            float4 a1 = *(float4*)&As[kk][tm + 4];
            float4 b4 = *(float4*)&Bs[kk][tn];
            float avv[8] = {a0.x, a0.y, a0.z, a0.w, a1.x, a1.y, a1.z, a1.w};
            float bvv[4] = {b4.x, b4.y, b4.z, b4.w};
#pragma unroll
            for (int i = 0; i < 8; i++)
#pragma unroll
                for (int j2 = 0; j2 < 4; j2++) acc[i][j2] += avv[i] * bvv[j2];
        }
    }
#pragma unroll
    for (int r = 0; r < 8; r++) {
        int s = s0 + tm + r;
        float4 ov;
        float* po = &ov.x;
#pragma unroll
        for (int c2 = 0; c2 < 4; c2++) {
            int n = n0 + tn + c2;
            po[c2] = (n < 200) ? tanhf(acc[r][c2] + __ldg(&b1[n])) : 0.f;
        }
        if (n0 + tn < 200)
            *(float4*)&g_hid[(size_t)s * 200 + n0 + tn] = ov;
    }
}

// ---------------- MLP2 + softmax: one warp per sample ----------------
__global__ __launch_bounds__(128) void k_mlp2(
    const float* __restrict__ w2, const float* __restrict__ b2, float* __restrict__ out)
{
    __shared__ float w2s[800];
    __shared__ float b2s[4];
    const int tid = threadIdx.x;
    for (int i = tid; i < 800; i += 128) w2s[i] = w2[i];
    if (tid < 4) b2s[tid] = b2[tid];
    __syncthreads();
    const int warp = tid >> 5, lane = tid & 31;
    const int s = blockIdx.x * 4 + warp;
    const float* hr = g_hid + (size_t)s * 200;
    float a0 = 0.f, a1 = 0.f, a2 = 0.f, a3 = 0.f;
    for (int k = lane; k < 200; k += 32) {
        float h = hr[k];
        a0 += h * w2s[k];
        a1 += h * w2s[200 + k];
        a2 += h * w2s[400 + k];
        a3 += h * w2s[600 + k];
    }
#pragma unroll
    for (int o = 16; o > 0; o >>= 1) {
        a0 += __shfl_down_sync(0xffffffffu, a0, o);
        a1 += __shfl_down_sync(0xffffffffu, a1, o);
        a2 += __shfl_down_sync(0xffffffffu, a2, o);
        a3 += __shfl_down_sync(0xffffffffu, a3, o);
    }
    if (lane == 0) {
        float l0 = a0 + b2s[0], l1 = a1 + b2s[1], l2 = a2 + b2s[2], l3 = a3 + b2s[3];
        float m = fmaxf(fmaxf(l0, l1), fmaxf(l2, l3));
        float e0 = expf(l0 - m), e1 = expf(l1 - m), e2 = expf(l2 - m), e3 = expf(l3 - m);
        float inv = 1.f / (e0 + e1 + e2 + e3);
        float4 r = make_float4(e0 * inv, e1 * inv, e2 * inv, e3 * inv);
        *(float4*)&out[(size_t)s * 4] = r;
    }
}

extern "C" void kernel_launch(void* const* d_in, const int* in_sizes, int n_in,
                              void* d_out, int out_size)
{
    const int* tokens = (const int*)d_in[0];
    const int* paths = (const int*)d_in[1];
    const float* emb = (const float*)d_in[2];
    const float* wih0f = (const float*)d_in[3];
    const float* whh0f = (const float*)d_in[4];
    const float* bih0f = (const float*)d_in[5];
    const float* bhh0f = (const float*)d_in[6];
    const float* wih0b = (const float*)d_in[7];
    const float* whh0b = (const float*)d_in[8];
    const float* bih0b = (const float*)d_in[9];
    const float* bhh0b = (const float*)d_in[10];
    const float* wih1f = (const float*)d_in[11];
    const float* whh1f = (const float*)d_in[12];
    const float* bih1f = (const float*)d_in[13];
    const float* bhh1f = (const float*)d_in[14];
    const float* wih1b = (const float*)d_in[15];
    const float* whh1b = (const float*)d_in[16];
    const float* bih1b = (const float*)d_in[17];
    const float* bhh1b = (const float*)d_in[18];
    const float* w1 = (const float*)d_in[19];
    const float* b1 = (const float*)d_in[20];
    const float* w2 = (const float*)d_in[21];
    const float* b2 = (const float*)d_in[22];
    float* out = (float*)d_out;

    cudaFuncSetAttribute(k_recur_mma, cudaFuncAttributeMaxDynamicSharedMemorySize, RSMEM);

    k_embsplit<<<TT, 256>>>(tokens, emb);                               // launch 1
    dim3 gw((896 * KP1 + 255) / 256, 8);
    k_prepw<<<gw, 256>>>(wih0f, wih0b, wih1f, wih1b,
                         whh0f, whh0b, whh1f, whh1b);                   // launch 2

    dim3 gg(7, TT, 2);
    k_gemm_mma<<<gg, 256>>>(0, bih0f, bhh0f, bih0b, bhh0b);             // launch 3
    k_recur_mma<<<RCN, 256, RSMEM>>>(0);                                // launch 4 (profiled)
    k_gemm_mma<<<gg, 256>>>(1, bih1f, bhh1f, bih1b, bhh1b);             // launch 5
    k_recur_mma<<<RCN, 256, RSMEM>>>(1);                                // launch 6

    dim3 g4(NSAMP / 128, 4);
    k_gather_mlp1<<<g4, 256>>>(paths, w1, b1);
    k_mlp2<<<NSAMP / 4, 128>>>(w2, b2, out);
}